// round 15
// baseline (speedup 1.0000x reference)
#include <cuda_runtime.h>
#include <cuda_bf16.h>
#include <cstdint>

// Problem constants
#define BB 2
#define LL 2048
#define HH 1024
#define NHH 16
#define HDD 64
#define MM (BB*LL)   // 4096
#define BH (BB*NHH)  // 32
#define KP 512       // k-pairs per 1024 row
#define LOG2E 1.4426950408889634f

// ---------------- scratch (static device globals; no allocation) -------------
__device__ uint32_t g_xh[MM*KP],  g_xl[MM*KP];    // x          [m][kp]
__device__ uint32_t g_wh[4*HH*KP], g_wl[4*HH*KP]; // weights^T  [mat][n][kp]
__device__ uint32_t g_qh[BH*LL*32], g_ql[BH*LL*32];   // Q [bh][l][dp]
__device__ uint32_t g_kh[BH*LL*32], g_kl[BH*LL*32];   // K [bh][l][dp]
__device__ uint32_t g_vh[BH*HDD*(LL/2)], g_vl[BH*HDD*(LL/2)]; // V [bh][d][lp]
__device__ uint32_t g_atth[MM*KP], g_attl[MM*KP]; // attn out  [m][kp]
__device__ float g_bias[BH*LL];                   // [bh][k]  (pre-scaled by log2e)

// ================= helpers ====================================================
__device__ __forceinline__ uint32_t smem_u32(const void* p) {
    uint32_t a;
    asm("{ .reg .u64 t; cvta.to.shared.u64 t, %1; cvt.u32.u64 %0, t; }"
        : "=r"(a) : "l"(p));
    return a;
}
__device__ __forceinline__ void ldsm4(uint32_t* r, uint32_t addr) {
    asm volatile("ldmatrix.sync.aligned.m8n8.x4.shared.b16 {%0,%1,%2,%3}, [%4];"
        : "=r"(r[0]), "=r"(r[1]), "=r"(r[2]), "=r"(r[3]) : "r"(addr));
}
__device__ __forceinline__ void mma16816(float* c, const uint32_t* a,
                                         uint32_t b0, uint32_t b1) {
    asm volatile(
        "mma.sync.aligned.m16n8k16.row.col.f32.bf16.bf16.f32 "
        "{%0,%1,%2,%3}, {%4,%5,%6,%7}, {%8,%9}, {%0,%1,%2,%3};"
        : "+f"(c[0]), "+f"(c[1]), "+f"(c[2]), "+f"(c[3])
        : "r"(a[0]), "r"(a[1]), "r"(a[2]), "r"(a[3]), "r"(b0), "r"(b1));
}
__device__ __forceinline__ uint32_t pack2(float x, float y) {
    __nv_bfloat162 h = __floats2bfloat162_rn(x, y);
    return *reinterpret_cast<uint32_t*>(&h);
}
__device__ __forceinline__ float bhi(float x) {
    return __bfloat162float(__float2bfloat16(x));
}
__device__ __forceinline__ float ex2(float x) {
    float r;
    asm("ex2.approx.f32 %0, %1;" : "=f"(r) : "f"(x));
    return r;
}
// fast split of a float pair: hi = bit-truncated bf16 (PRMT pack), lo = exact residual (rn)
__device__ __forceinline__ void splitpair(float a, float b, uint32_t& hp, uint32_t& lp) {
    uint32_t ua = __float_as_uint(a), ub = __float_as_uint(b);
    asm("prmt.b32 %0, %1, %2, 0x7632;" : "=r"(hp) : "r"(ua), "r"(ub));
    float ha = __uint_as_float(ua & 0xFFFF0000u);
    float hb = __uint_as_float(ub & 0xFFFF0000u);
    float la = a - ha, lb = b - hb;
    asm("cvt.rn.bf16x2.f32 %0, %1, %2;" : "=r"(lp) : "f"(lb), "f"(la));
}
__device__ __forceinline__ void cpa16(uint32_t sm, const void* g) {
    asm volatile("cp.async.cg.shared.global [%0], [%1], 16;"
                 :: "r"(sm), "l"(g) : "memory");
}
#define CPA_COMMIT() asm volatile("cp.async.commit_group;" ::: "memory")
#define CPA_WAIT0()  asm volatile("cp.async.wait_group 0;" ::: "memory")

// ---------------- x split (fp32 -> packed bf16 hi/lo) ------------------------
__global__ void xsplit_kernel(const float* __restrict__ x)
{
    int idx = blockIdx.x * 256 + threadIdx.x;   // 2M pairs
    float2 v = *(const float2*)&x[(size_t)idx * 2];
    float h0 = bhi(v.x), h1 = bhi(v.y);
    g_xh[idx] = pack2(h0, h1);
    g_xl[idx] = pack2(v.x - h0, v.y - h1);
}

// ---------------- weight transpose + split -----------------------------------
__global__ void wtrans_kernel(const float* __restrict__ W0, const float* __restrict__ W1,
                              const float* __restrict__ W2, const float* __restrict__ W3)
{
    __shared__ float t[32][33];
    int mat = blockIdx.z;
    const float* src = (mat == 0) ? W0 : (mat == 1) ? W1 : (mat == 2) ? W2 : W3;
    int x0 = blockIdx.x * 32, y0 = blockIdx.y * 32;
    int tx = threadIdx.x, ty = threadIdx.y;  // 32 x 8
    #pragma unroll
    for (int i = 0; i < 32; i += 8)
        t[ty + i][tx] = src[(size_t)(y0 + ty + i) * HH + x0 + tx];  // t[k'][n']
    __syncthreads();
    int tid = ty * 32 + tx;
    #pragma unroll
    for (int it = 0; it < 2; it++) {
        int e = tid + 256 * it;            // 0..511 = 32 n x 16 kp
        int np = e >> 4, kp = e & 15;
        float v0 = t[2 * kp][np], v1 = t[2 * kp + 1][np];
        float h0 = bhi(v0), h1 = bhi(v1);
        size_t off = (size_t)mat * HH * KP + (size_t)(x0 + np) * KP + (y0 >> 1) + kp;
        g_wh[off] = pack2(h0, h1);
        g_wl[off] = pack2(v0 - h0, v1 - h1);
    }
}

// ---------------- gate / additive-bias kernel --------------------------------
__global__ void gate_bias_kernel(const float* __restrict__ x,
                                 const float* __restrict__ amask,
                                 const int*   __restrict__ err,
                                 const float* __restrict__ Wg,
                                 const float* __restrict__ bg,
                                 const float* __restrict__ dbias)
{
    __shared__ float red[128];
    int row = blockIdx.x;
    int tid = threadIdx.x;
    int col = tid & 15;
    int seg = tid >> 4;
    const float* xr = x + row * HH;
    const int kbase = seg * 128;
    float acc = 0.f;
    #pragma unroll 8
    for (int kk = 0; kk < 128; kk++)
        acc += xr[kbase + kk] * Wg[(kbase + kk) * NHH + col];
    red[tid] = acc;
    __syncthreads();
    if (tid < 64) red[tid] += red[tid + 64];
    __syncthreads();
    if (tid < 32) red[tid] += red[tid + 32];
    __syncthreads();
    if (tid < 16) {
        float v = red[tid] + red[tid + 16] + bg[tid];
        float g = 1.f / (1.f + __expf(-v));
        int b = row >> 11;
        int l = row & (LL - 1);
        float bias = ((float)err[row] * g + amask[row] + dbias[tid]) * LOG2E;
        g_bias[(b * NHH + tid) * LL + l] = bias;
    }
}

// ---------------- pipelined bf16-split tensor-core GEMM ----------------------
#define TGM 128
#define TGN 128
#define ROWB 80
#define OFF_AHI 0
#define OFF_ALO 10240
#define OFF_BHI 20480
#define OFF_BLO 30720
#define STG 40960
#define TG_SMEM (2 * STG)            // 81920; epilogue (67584) reuses it

struct TGArgs {
    const uint32_t *Ah, *Al, *Bh, *Bl;
    const float* bias;
};

template<int MODE>
__device__ __forceinline__ void tgemm_body(const TGArgs& ar, float* out,
                                           int n0, int m0, char* dynsmem)
{
    uint32_t sb = smem_u32(dynsmem);
    int tid = threadIdx.x;
    int lane = tid & 31;
    int wid = tid >> 5;
    int m_base = (wid >> 2) * 64;
    int n_base = (wid & 3) * 32;

    int t = lane >> 3;
    uint32_t a_rel = OFF_AHI +
        (uint32_t)((m_base + (t & 1) * 8 + (lane & 7)) * ROWB + (t >> 1) * 16);
    uint32_t b_rel = OFF_BHI +
        (uint32_t)((n_base + (t >> 1) * 8 + (lane & 7)) * ROWB + (t & 1) * 16);

    float acc[4][4][4];
    #pragma unroll
    for (int i = 0; i < 4; i++)
        #pragma unroll
        for (int j = 0; j < 4; j++)
            #pragma unroll
            for (int r = 0; r < 4; r++) acc[i][j][r] = 0.f;

    auto load_stage = [&](int c) {
        uint32_t sta = sb + (c & 1) * STG;
        int kp0 = c * 16;
        #pragma unroll
        for (int i = 0; i < 2; i++) {
            int idx = tid + 256 * i;         // 0..511
            int row = idx >> 2, seg = idx & 3;
            uint32_t so = (uint32_t)(row * ROWB + seg * 16);
            size_t ga = ((size_t)(m0 + row) * KP + kp0 + seg * 4) * 4;
            size_t gb = ((size_t)(n0 + row) * KP + kp0 + seg * 4) * 4;
            cpa16(sta + OFF_AHI + so, (const char*)ar.Ah + ga);
            cpa16(sta + OFF_ALO + so, (const char*)ar.Al + ga);
            cpa16(sta + OFF_BHI + so, (const char*)ar.Bh + gb);
            cpa16(sta + OFF_BLO + so, (const char*)ar.Bl + gb);
        }
        CPA_COMMIT();
    };

    load_stage(0);
    for (int c = 0; c < 32; c++) {
        CPA_WAIT0();
        __syncthreads();
        if (c < 31) load_stage(c + 1);   // overlaps with MMAs below
        uint32_t stb = sb + (c & 1) * STG;
        #pragma unroll
        for (int kk = 0; kk < 2; kk++) {
            uint32_t ah[4][4], al[4][4], bh4[2][4], bl4[2][4];
            #pragma unroll
            for (int mt = 0; mt < 4; mt++) {
                uint32_t ad = stb + a_rel + mt * (16 * ROWB) + kk * 32;
                ldsm4(ah[mt], ad);
                ldsm4(al[mt], ad + (OFF_ALO - OFF_AHI));
            }
            #pragma unroll
            for (int np = 0; np < 2; np++) {
                uint32_t bd = stb + b_rel + np * (16 * ROWB) + kk * 32;
                ldsm4(bh4[np], bd);
                ldsm4(bl4[np], bd + (OFF_BLO - OFF_BHI));
            }
            // term-major order: same-accumulator reuse distance = 4 issues
            #pragma unroll
            for (int mt = 0; mt < 4; mt++) {
                #pragma unroll
                for (int nt = 0; nt < 4; nt++) {
                    int np = nt >> 1, e = (nt & 1) * 2;
                    mma16816(acc[mt][nt], ah[mt], bh4[np][e], bh4[np][e + 1]);
                }
                #pragma unroll
                for (int nt = 0; nt < 4; nt++) {
                    int np = nt >> 1, e = (nt & 1) * 2;
                    mma16816(acc[mt][nt], ah[mt], bl4[np][e], bl4[np][e + 1]);
                }
                #pragma unroll
                for (int nt = 0; nt < 4; nt++) {
                    int np = nt >> 1, e = (nt & 1) * 2;
                    mma16816(acc[mt][nt], al[mt], bh4[np][e], bh4[np][e + 1]);
                }
            }
        }
    }
    __syncthreads();

    // ---- epilogue: frags -> smem staging (bias, mode scale) ----
    float* sD = (float*)dynsmem;
    int g = lane >> 2, cb = (lane & 3) * 2;
    #pragma unroll
    for (int mt = 0; mt < 4; mt++)
        #pragma unroll
        for (int nt = 0; nt < 4; nt++)
            #pragma unroll
            for (int r = 0; r < 4; r++) {
                int row = m_base + mt * 16 + (r >> 1) * 8 + g;
                int col = n_base + nt * 8 + cb + (r & 1);
                float v = acc[mt][nt][r] + ar.bias[n0 + col];
                if (MODE == 0) v *= 0.125f * LOG2E;   // 1/sqrt(64) and exp2 domain
                sD[row * 132 + col] = v;
            }
    __syncthreads();

    // ---- smem -> global ----
    int b  = m0 >> 11;
    int l0 = m0 & (LL - 1);
    if (MODE == 0 || MODE == 1) {
        uint32_t* dh = (MODE == 0) ? g_qh : g_kh;
        uint32_t* dl = (MODE == 0) ? g_ql : g_kl;
        for (int idx = tid; idx < 8192; idx += 256) {
            int dp = idx & 31;
            int hseg = (idx >> 5) & 1;
            int mi = idx >> 6;
            int nl = hseg * 64 + dp * 2;
            float v0 = sD[mi * 132 + nl], v1 = sD[mi * 132 + nl + 1];
            float h0 = bhi(v0), h1 = bhi(v1);
            int n = n0 + nl, h = n >> 6;
            size_t o = (size_t)((b * NHH + h) * LL + l0 + mi) * 32 + dp;
            dh[o] = pack2(h0, h1);
            dl[o] = pack2(v0 - h0, v1 - h1);
        }
    } else if (MODE == 2) {
        for (int idx = tid; idx < 8192; idx += 256) {
            int lp = idx & 63;
            int nl = idx >> 6;
            float v0 = sD[(2 * lp) * 132 + nl], v1 = sD[(2 * lp + 1) * 132 + nl];
            float h0 = bhi(v0), h1 = bhi(v1);
            int n = n0 + nl, h = n >> 6, d = n & 63;
            size_t o = (size_t)((b * NHH + h) * HDD + d) * (LL / 2) + l0 / 2 + lp;
            g_vh[o] = pack2(h0, h1);
            g_vl[o] = pack2(v0 - h0, v1 - h1);
        }
    } else {
        for (int idx = tid; idx < TGM * TGN; idx += 256) {
            int nl = idx & 127, mi = idx >> 7;
            out[(size_t)(m0 + mi) * HH + n0 + nl] = sD[mi * 132 + nl];
        }
    }
}

__global__ void __launch_bounds__(256)
qkv_kernel(const float* __restrict__ bq, const float* __restrict__ bk,
           const float* __restrict__ bv)
{
    extern __shared__ char dynsmem[];
    int mode = blockIdx.z;
    TGArgs ar;
    ar.Ah = g_xh; ar.Al = g_xl;
    ar.Bh = g_wh + (size_t)mode * HH * KP;
    ar.Bl = g_wl + (size_t)mode * HH * KP;
    ar.bias = (mode == 0) ? bq : (mode == 1) ? bk : bv;
    int n0 = blockIdx.x * TGN, m0 = blockIdx.y * TGM;
    if (mode == 0)      tgemm_body<0>(ar, nullptr, n0, m0, dynsmem);
    else if (mode == 1) tgemm_body<1>(ar, nullptr, n0, m0, dynsmem);
    else                tgemm_body<2>(ar, nullptr, n0, m0, dynsmem);
}

__global__ void __launch_bounds__(256)
oproj_kernel(const float* __restrict__ bo, float* __restrict__ out)
{
    extern __shared__ char dynsmem[];
    TGArgs ar;
    ar.Ah = g_atth; ar.Al = g_attl;
    ar.Bh = g_wh + (size_t)3 * HH * KP;
    ar.Bl = g_wl + (size_t)3 * HH * KP;
    ar.bias = bo;
    tgemm_body<3>(ar, out, blockIdx.x * TGN, blockIdx.y * TGM, dynsmem);
}

// ---------------- tensor-core flash attention (256 thr, 128 q-rows) -----------
#define FROWB 144
#define FQH 0
#define FQL 18432                 // Q: 128 rows x 144 per half
#define FSTG0 36864               // per-stage: KH +0, KL +9216, VH +18432, VL +27648
#define FSTGB 36864
#define FBIAS (FSTG0 + 2*FSTGB)   // 110592; 2 x 256B
#define FL_SMEM (FBIAS + 512)     // 111104

__global__ void __launch_bounds__(256, 2)
flash_kernel()
{
    extern __shared__ char fsm[];
    uint32_t sb = smem_u32(fsm);
    int tid = threadIdx.x;
    int lane = tid & 31;
    int wid = tid >> 5;          // 0..7, each warp owns 16 q-rows
    int bh = blockIdx.y;
    int q0 = blockIdx.x * 128;

    const char* qh = (const char*)g_qh;
    const char* ql = (const char*)g_ql;
    const char* kh = (const char*)g_kh;
    const char* kl = (const char*)g_kl;
    const char* vh = (const char*)g_vh;
    const char* vl = (const char*)g_vl;

    // K/V/bias stage loader (async): 2048 16B-chunks, 8 per thread
    auto load_kv = [&](int c) {
        uint32_t dst = sb + FSTG0 + (c & 1) * FSTGB;
        int k0 = c * 64;
        #pragma unroll
        for (int i = 0; i < 8; i++) {
            int idx = tid + i * 256;         // 0..2047
            int arr = idx >> 9;              // 0:KH 1:KL 2:VH 3:VL
            int e = idx & 511;
            int r = e >> 3, q8 = e & 7;
            uint32_t so = (uint32_t)(arr * 9216 + r * FROWB + q8 * 16);
            if (arr < 2) {
                size_t gk = (size_t)(bh * LL + k0 + r) * 128 + q8 * 16;
                cpa16(dst + so, (arr == 0 ? kh : kl) + gk);
            } else {
                size_t gv = (size_t)(bh * HDD + r) * (LL * 2) + k0 * 2 + q8 * 16;
                cpa16(dst + so, (arr == 2 ? vh : vl) + gv);
            }
        }
        if (tid < 16)
            cpa16(sb + FBIAS + (c & 1) * 256 + tid * 16,
                  (const char*)g_bias + (size_t)bh * LL * 4 + c * 256 + tid * 16);
        CPA_COMMIT();
    };

    // Q tile (once, synchronous): 128 rows hi+lo = 2048 chunks
    #pragma unroll
    for (int i = 0; i < 8; i++) {
        int idx = tid + i * 256;
        int half = idx >> 10;
        int e = idx & 1023;
        int r = e >> 3, q8 = e & 7;
        size_t go = (size_t)(bh * LL + q0 + r) * 128 + q8 * 16;
        *(uint4*)(fsm + (half ? FQL : FQH) + r * FROWB + q8 * 16) =
            *(const uint4*)((half ? ql : qh) + go);
    }
    load_kv(0);
    __syncthreads();   // Q visible for fragment hoist

    int t8 = lane >> 3;
    uint32_t qa = sb + FQH +
        (uint32_t)((wid * 16 + (t8 & 1) * 8 + (lane & 7)) * FROWB + (t8 >> 1) * 16);
    uint32_t kb_rel =
        (uint32_t)(((t8 >> 1) * 8 + (lane & 7)) * FROWB + (t8 & 1) * 16);

    // hoist Q fragments (Q smem never overwritten)
    uint32_t qfh[4][4], qfl[4][4];
    #pragma unroll
    for (int kk = 0; kk < 4; kk++) {
        ldsm4(qfh[kk], qa + kk * 32);
        ldsm4(qfl[kk], qa + kk * 32 + (FQL - FQH));
    }

    float o[8][4];
    #pragma unroll
    for (int i = 0; i < 8; i++)
        #pragma unroll
        for (int r = 0; r < 4; r++) o[i][r] = 0.f;
    float m0r = -1e30f, m1r = -1e30f, ls0 = 0.f, ls1 = 0.f;

    for (int c = 0; c < 32; c++) {
        CPA_WAIT0();             // stage c fully arrived (only outstanding group)
        __syncthreads();         // stage c visible to all; all done reading stage c-1
        if (c < 31) load_kv(c + 1);   // overwrite stage c-1 buffer; overlaps compute

        uint32_t stg = sb + FSTG0 + (c & 1) * FSTGB;
        uint32_t kb = stg + kb_rel;
        uint32_t vb = stg + 18432 + kb_rel;
        const float* sbias = (const float*)(fsm + FBIAS + (c & 1) * 256);
        int cb = (lane & 3) * 2;

        // ---- S = Q K^T (3-term bf16 split), bias pre-loaded as accumulator ----
        float s[8][4];
        #pragma unroll
        for (int nf = 0; nf < 8; nf++) {
            float b0 = sbias[nf * 8 + cb], b1 = sbias[nf * 8 + cb + 1];
            s[nf][0] = b0; s[nf][1] = b1;
            s[nf][2] = b0; s[nf][3] = b1;
        }

        #pragma unroll
        for (int kk = 0; kk < 4; kk++) {
            #pragma unroll
            for (int nb = 0; nb < 4; nb++) {
                uint32_t bh4[4], bl4[4];
                uint32_t ba = kb + nb * (16 * FROWB) + kk * 32;
                ldsm4(bh4, ba);
                ldsm4(bl4, ba + 9216);
                // alternate the two accumulators: same-acc distance = 2 issues
                mma16816(s[2 * nb],     qfh[kk], bh4[0], bh4[1]);
                mma16816(s[2 * nb + 1], qfh[kk], bh4[2], bh4[3]);
                mma16816(s[2 * nb],     qfh[kk], bl4[0], bl4[1]);
                mma16816(s[2 * nb + 1], qfh[kk], bl4[2], bl4[3]);
                mma16816(s[2 * nb],     qfl[kk], bh4[0], bh4[1]);
                mma16816(s[2 * nb + 1], qfl[kk], bh4[2], bh4[3]);
            }
        }

        // ---- online softmax in exp2 domain ----
        float mx0 = -1e30f, mx1 = -1e30f;
        #pragma unroll
        for (int nf = 0; nf < 8; nf++) {
            mx0 = fmaxf(mx0, fmaxf(s[nf][0], s[nf][1]));
            mx1 = fmaxf(mx1, fmaxf(s[nf][2], s[nf][3]));
        }
        mx0 = fmaxf(mx0, __shfl_xor_sync(0xffffffffu, mx0, 1));
        mx0 = fmaxf(mx0, __shfl_xor_sync(0xffffffffu, mx0, 2));
        mx1 = fmaxf(mx1, __shfl_xor_sync(0xffffffffu, mx1, 1));
        mx1 = fmaxf(mx1, __shfl_xor_sync(0xffffffffu, mx1, 2));
        float mn0 = fmaxf(m0r, mx0), mn1 = fmaxf(m1r, mx1);
        float c0 = ex2(m0r - mn0), c1 = ex2(m1r - mn1);
        m0r = mn0; m1r = mn1;
        ls0 *= c0; ls1 *= c1;
        #pragma unroll
        for (int nf = 0; nf < 8; nf++) {
            o[nf][0] *= c0; o[nf][1] *= c0;
            o[nf][2] *= c1; o[nf][3] *= c1;
        }
        float rs0 = 0.f, rs1 = 0.f;
        #pragma unroll
        for (int nf = 0; nf < 8; nf++) {
            s[nf][0] = ex2(s[nf][0] - mn0);
            s[nf][1] = ex2(s[nf][1] - mn0);
            s[nf][2] = ex2(s[nf][2] - mn1);
            s[nf][3] = ex2(s[nf][3] - mn1);
            rs0 += s[nf][0] + s[nf][1];
            rs1 += s[nf][2] + s[nf][3];
        }
        rs0 += __shfl_xor_sync(0xffffffffu, rs0, 1);
        rs0 += __shfl_xor_sync(0xffffffffu, rs0, 2);
        rs1 += __shfl_xor_sync(0xffffffffu, rs1, 1);
        rs1 += __shfl_xor_sync(0xffffffffu, rs1, 2);
        ls0 += rs0; ls1 += rs1;

        // ---- O += P V (P split via truncation/PRMT) ----
        #pragma unroll
        for (int j = 0; j < 4; j++) {
            uint32_t aph[4], apl[4];
            splitpair(s[2*j][0],   s[2*j][1],   aph[0], apl[0]);
            splitpair(s[2*j][2],   s[2*j][3],   aph[1], apl[1]);
            splitpair(s[2*j+1][0], s[2*j+1][1], aph[2], apl[2]);
            splitpair(s[2*j+1][2], s[2*j+1][3], aph[3], apl[3]);
            #pragma unroll
            for (int nb = 0; nb < 4; nb++) {
                uint32_t vh4[4], vl4[4];
                uint32_t va = vb + nb * (16 * FROWB) + j * 32;
                ldsm4(vh4, va);
                ldsm4(vl4, va + 9216);
                // alternate the two accumulators: same-acc distance = 2 issues
                mma16816(o[2 * nb],     aph, vh4[0], vh4[1]);
                mma16816(o[2 * nb + 1], aph, vh4[2], vh4[3]);
                mma16816(o[2 * nb],     aph, vl4[0], vl4[1]);
                mma16816(o[2 * nb + 1], aph, vl4[2], vl4[3]);
                mma16816(o[2 * nb],     apl, vh4[0], vh4[1]);
                mma16816(o[2 * nb + 1], apl, vh4[2], vh4[3]);
            }
        }
    }

    // ---- finalize: O /= l, write split bf16 directly (O-proj A operand) ----
    int b = bh >> 4;
    int h = bh & 15;
    float i0 = 1.f / ls0, i1 = 1.f / ls1;
    int g = lane >> 2, cb = (lane & 3) * 2;
    int row0 = q0 + wid * 16 + g;
    #pragma unroll
    for (int nf = 0; nf < 8; nf++) {
        int colp = (h * HDD + nf * 8 + cb) >> 1;
        float a0 = o[nf][0] * i0, a1 = o[nf][1] * i0;
        float b0 = o[nf][2] * i1, b1 = o[nf][3] * i1;
        float ah0 = bhi(a0), ah1 = bhi(a1), bh0 = bhi(b0), bh1 = bhi(b1);
        size_t r0o = (size_t)(b * LL + row0) * KP + colp;
        size_t r1o = (size_t)(b * LL + row0 + 8) * KP + colp;
        g_atth[r0o] = pack2(ah0, ah1);
        g_attl[r0o] = pack2(a0 - ah0, a1 - ah1);
        g_atth[r1o] = pack2(bh0, bh1);
        g_attl[r1o] = pack2(b0 - bh0, b1 - bh1);
    }
}

// ---------------- launch ------------------------------------------------------
extern "C" void kernel_launch(void* const* d_in, const int* in_sizes, int n_in,
                              void* d_out, int out_size)
{
    const float* x     = (const float*)d_in[0];
    const float* amask = (const float*)d_in[1];
    const int*   err   = (const int*)  d_in[2];
    const float* Wq    = (const float*)d_in[3];
    const float* bq    = (const float*)d_in[4];
    const float* Wk    = (const float*)d_in[5];
    const float* bk    = (const float*)d_in[6];
    const float* Wv    = (const float*)d_in[7];
    const float* bv    = (const float*)d_in[8];
    const float* Wo    = (const float*)d_in[9];
    const float* bo    = (const float*)d_in[10];
    const float* dbias = (const float*)d_in[11];
    const float* Wg    = (const float*)d_in[12];
    const float* bg    = (const float*)d_in[13];
    float* out = (float*)d_out;

    cudaFuncSetAttribute(qkv_kernel,   cudaFuncAttributeMaxDynamicSharedMemorySize, TG_SMEM);
    cudaFuncSetAttribute(oproj_kernel, cudaFuncAttributeMaxDynamicSharedMemorySize, TG_SMEM);
    cudaFuncSetAttribute(flash_kernel, cudaFuncAttributeMaxDynamicSharedMemorySize, FL_SMEM);

    xsplit_kernel<<<MM * HH / 512, 256>>>(x);

    dim3 tb(32, 8);
    dim3 tg(HH / 32, HH / 32, 4);
    wtrans_kernel<<<tg, tb>>>(Wq, Wk, Wv, Wo);

    gate_bias_kernel<<<MM, 128>>>(x, amask, err, Wg, bg, dbias);

    dim3 qgrid(HH / TGN, MM / TGM, 3);   // 768 CTAs
    qkv_kernel<<<qgrid, 256, TG_SMEM>>>(bq, bk, bv);

    dim3 fgrid(LL / 128, BH);            // 512 CTAs, 256 threads
    flash_kernel<<<fgrid, 256, FL_SMEM>>>();

    dim3 ogrid(HH / TGN, MM / TGM);      // 256 CTAs
    oproj_kernel<<<ogrid, 256, TG_SMEM>>>(bo, out);
}

// round 17
// speedup vs baseline: 1.0697x; 1.0697x over previous
#include <cuda_runtime.h>
#include <cuda_bf16.h>
#include <cuda_fp16.h>
#include <cstdint>

// Problem constants
#define BB 2
#define LL 2048
#define HH 1024
#define NHH 16
#define HDD 64
#define MM (BB*LL)   // 4096
#define BH (BB*NHH)  // 32
#define KP 512       // k-pairs per 1024 row
#define LOG2E 1.4426950408889634f

// ---------------- scratch (static device globals; no allocation) -------------
__device__ uint32_t g_xh[MM*KP],  g_xl[MM*KP];    // x          [m][kp]
__device__ uint32_t g_wh[4*HH*KP], g_wl[4*HH*KP]; // weights^T  [mat][n][kp]
__device__ uint32_t g_qh[BH*LL*32], g_ql[BH*LL*32];   // Q [bh][l][dp] bf16 hi/lo
__device__ uint32_t g_kh[BH*LL*32], g_kl[BH*LL*32];   // K [bh][l][dp] bf16 hi/lo
__device__ uint32_t g_vh[BH*HDD*(LL/2)];          // V [bh][d][lp] fp16 SINGLE
__device__ uint32_t g_atth[MM*KP], g_attl[MM*KP]; // attn out  [m][kp] bf16 hi/lo
__device__ float g_bias[BH*LL];                   // [bh][k]  (pre-scaled by log2e)

// ================= helpers ====================================================
__device__ __forceinline__ uint32_t smem_u32(const void* p) {
    uint32_t a;
    asm("{ .reg .u64 t; cvta.to.shared.u64 t, %1; cvt.u32.u64 %0, t; }"
        : "=r"(a) : "l"(p));
    return a;
}
__device__ __forceinline__ void ldsm4(uint32_t* r, uint32_t addr) {
    asm volatile("ldmatrix.sync.aligned.m8n8.x4.shared.b16 {%0,%1,%2,%3}, [%4];"
        : "=r"(r[0]), "=r"(r[1]), "=r"(r[2]), "=r"(r[3]) : "r"(addr));
}
__device__ __forceinline__ void mma16816(float* c, const uint32_t* a,
                                         uint32_t b0, uint32_t b1) {
    asm volatile(
        "mma.sync.aligned.m16n8k16.row.col.f32.bf16.bf16.f32 "
        "{%0,%1,%2,%3}, {%4,%5,%6,%7}, {%8,%9}, {%0,%1,%2,%3};"
        : "+f"(c[0]), "+f"(c[1]), "+f"(c[2]), "+f"(c[3])
        : "r"(a[0]), "r"(a[1]), "r"(a[2]), "r"(a[3]), "r"(b0), "r"(b1));
}
__device__ __forceinline__ void mma16816h(float* c, const uint32_t* a,
                                          uint32_t b0, uint32_t b1) {
    asm volatile(
        "mma.sync.aligned.m16n8k16.row.col.f32.f16.f16.f32 "
        "{%0,%1,%2,%3}, {%4,%5,%6,%7}, {%8,%9}, {%0,%1,%2,%3};"
        : "+f"(c[0]), "+f"(c[1]), "+f"(c[2]), "+f"(c[3])
        : "r"(a[0]), "r"(a[1]), "r"(a[2]), "r"(a[3]), "r"(b0), "r"(b1));
}
__device__ __forceinline__ uint32_t pack2(float x, float y) {
    __nv_bfloat162 h = __floats2bfloat162_rn(x, y);
    return *reinterpret_cast<uint32_t*>(&h);
}
__device__ __forceinline__ uint32_t pack2h(float x, float y) {
    __half2 h = __floats2half2_rn(x, y);
    return *reinterpret_cast<uint32_t*>(&h);
}
__device__ __forceinline__ float bhi(float x) {
    return __bfloat162float(__float2bfloat16(x));
}
__device__ __forceinline__ float ex2(float x) {
    float r;
    asm("ex2.approx.f32 %0, %1;" : "=f"(r) : "f"(x));
    return r;
}
// fp16 exact-ish split of a float pair: hi fp16x2 pack, lo = rn(residual)
__device__ __forceinline__ void splitpairh(float a, float b, uint32_t& hp, uint32_t& lp) {
    __half2 h = __floats2half2_rn(a, b);
    hp = *reinterpret_cast<uint32_t*>(&h);
    float2 hf = __half22float2(h);
    __half2 l = __floats2half2_rn(a - hf.x, b - hf.y);
    lp = *reinterpret_cast<uint32_t*>(&l);
}
__device__ __forceinline__ void cpa16(uint32_t sm, const void* g) {
    asm volatile("cp.async.cg.shared.global [%0], [%1], 16;"
                 :: "r"(sm), "l"(g) : "memory");
}
#define CPA_COMMIT() asm volatile("cp.async.commit_group;" ::: "memory")
#define CPA_WAIT0()  asm volatile("cp.async.wait_group 0;" ::: "memory")

// ---------------- x split (fp32 -> packed bf16 hi/lo) ------------------------
__global__ void xsplit_kernel(const float* __restrict__ x)
{
    int idx = blockIdx.x * 256 + threadIdx.x;   // 2M pairs
    float2 v = *(const float2*)&x[(size_t)idx * 2];
    float h0 = bhi(v.x), h1 = bhi(v.y);
    g_xh[idx] = pack2(h0, h1);
    g_xl[idx] = pack2(v.x - h0, v.y - h1);
}

// ---------------- weight transpose + split -----------------------------------
__global__ void wtrans_kernel(const float* __restrict__ W0, const float* __restrict__ W1,
                              const float* __restrict__ W2, const float* __restrict__ W3)
{
    __shared__ float t[32][33];
    int mat = blockIdx.z;
    const float* src = (mat == 0) ? W0 : (mat == 1) ? W1 : (mat == 2) ? W2 : W3;
    int x0 = blockIdx.x * 32, y0 = blockIdx.y * 32;
    int tx = threadIdx.x, ty = threadIdx.y;  // 32 x 8
    #pragma unroll
    for (int i = 0; i < 32; i += 8)
        t[ty + i][tx] = src[(size_t)(y0 + ty + i) * HH + x0 + tx];  // t[k'][n']
    __syncthreads();
    int tid = ty * 32 + tx;
    #pragma unroll
    for (int it = 0; it < 2; it++) {
        int e = tid + 256 * it;            // 0..511 = 32 n x 16 kp
        int np = e >> 4, kp = e & 15;
        float v0 = t[2 * kp][np], v1 = t[2 * kp + 1][np];
        float h0 = bhi(v0), h1 = bhi(v1);
        size_t off = (size_t)mat * HH * KP + (size_t)(x0 + np) * KP + (y0 >> 1) + kp;
        g_wh[off] = pack2(h0, h1);
        g_wl[off] = pack2(v0 - h0, v1 - h1);
    }
}

// ---------------- gate / additive-bias kernel --------------------------------
__global__ void gate_bias_kernel(const float* __restrict__ x,
                                 const float* __restrict__ amask,
                                 const int*   __restrict__ err,
                                 const float* __restrict__ Wg,
                                 const float* __restrict__ bg,
                                 const float* __restrict__ dbias)
{
    __shared__ float red[128];
    int row = blockIdx.x;
    int tid = threadIdx.x;
    int col = tid & 15;
    int seg = tid >> 4;
    const float* xr = x + row * HH;
    const int kbase = seg * 128;
    float acc = 0.f;
    #pragma unroll 8
    for (int kk = 0; kk < 128; kk++)
        acc += xr[kbase + kk] * Wg[(kbase + kk) * NHH + col];
    red[tid] = acc;
    __syncthreads();
    if (tid < 64) red[tid] += red[tid + 64];
    __syncthreads();
    if (tid < 32) red[tid] += red[tid + 32];
    __syncthreads();
    if (tid < 16) {
        float v = red[tid] + red[tid + 16] + bg[tid];
        float g = 1.f / (1.f + __expf(-v));
        int b = row >> 11;
        int l = row & (LL - 1);
        float bias = ((float)err[row] * g + amask[row] + dbias[tid]) * LOG2E;
        g_bias[(b * NHH + tid) * LL + l] = bias;
    }
}

// ---------------- pipelined bf16-split tensor-core GEMM ----------------------
#define TGM 128
#define TGN 128
#define ROWB 80
#define OFF_AHI 0
#define OFF_ALO 10240
#define OFF_BHI 20480
#define OFF_BLO 30720
#define STG 40960
#define TG_SMEM (2 * STG)            // 81920; epilogue (67584) reuses it

struct TGArgs {
    const uint32_t *Ah, *Al, *Bh, *Bl;
    const float* bias;
};

template<int MODE>
__device__ __forceinline__ void tgemm_body(const TGArgs& ar, float* out,
                                           int n0, int m0, char* dynsmem)
{
    uint32_t sb = smem_u32(dynsmem);
    int tid = threadIdx.x;
    int lane = tid & 31;
    int wid = tid >> 5;
    int m_base = (wid >> 2) * 64;
    int n_base = (wid & 3) * 32;

    int t = lane >> 3;
    uint32_t a_rel = OFF_AHI +
        (uint32_t)((m_base + (t & 1) * 8 + (lane & 7)) * ROWB + (t >> 1) * 16);
    uint32_t b_rel = OFF_BHI +
        (uint32_t)((n_base + (t >> 1) * 8 + (lane & 7)) * ROWB + (t & 1) * 16);

    float acc[4][4][4];
    #pragma unroll
    for (int i = 0; i < 4; i++)
        #pragma unroll
        for (int j = 0; j < 4; j++)
            #pragma unroll
            for (int r = 0; r < 4; r++) acc[i][j][r] = 0.f;

    auto load_stage = [&](int c) {
        uint32_t sta = sb + (c & 1) * STG;
        int kp0 = c * 16;
        #pragma unroll
        for (int i = 0; i < 2; i++) {
            int idx = tid + 256 * i;         // 0..511
            int row = idx >> 2, seg = idx & 3;
            uint32_t so = (uint32_t)(row * ROWB + seg * 16);
            size_t ga = ((size_t)(m0 + row) * KP + kp0 + seg * 4) * 4;
            size_t gb = ((size_t)(n0 + row) * KP + kp0 + seg * 4) * 4;
            cpa16(sta + OFF_AHI + so, (const char*)ar.Ah + ga);
            cpa16(sta + OFF_ALO + so, (const char*)ar.Al + ga);
            cpa16(sta + OFF_BHI + so, (const char*)ar.Bh + gb);
            cpa16(sta + OFF_BLO + so, (const char*)ar.Bl + gb);
        }
        CPA_COMMIT();
    };

    load_stage(0);
    for (int c = 0; c < 32; c++) {
        CPA_WAIT0();
        __syncthreads();
        if (c < 31) load_stage(c + 1);   // overlaps with MMAs below
        uint32_t stb = sb + (c & 1) * STG;
        #pragma unroll
        for (int kk = 0; kk < 2; kk++) {
            uint32_t ah[4][4], al[4][4], bh4[2][4], bl4[2][4];
            #pragma unroll
            for (int mt = 0; mt < 4; mt++) {
                uint32_t ad = stb + a_rel + mt * (16 * ROWB) + kk * 32;
                ldsm4(ah[mt], ad);
                ldsm4(al[mt], ad + (OFF_ALO - OFF_AHI));
            }
            #pragma unroll
            for (int np = 0; np < 2; np++) {
                uint32_t bd = stb + b_rel + np * (16 * ROWB) + kk * 32;
                ldsm4(bh4[np], bd);
                ldsm4(bl4[np], bd + (OFF_BLO - OFF_BHI));
            }
            #pragma unroll
            for (int mt = 0; mt < 4; mt++) {
                #pragma unroll
                for (int nt = 0; nt < 4; nt++) {
                    int np = nt >> 1, e = (nt & 1) * 2;
                    mma16816(acc[mt][nt], ah[mt], bh4[np][e], bh4[np][e + 1]);
                }
                #pragma unroll
                for (int nt = 0; nt < 4; nt++) {
                    int np = nt >> 1, e = (nt & 1) * 2;
                    mma16816(acc[mt][nt], ah[mt], bl4[np][e], bl4[np][e + 1]);
                }
                #pragma unroll
                for (int nt = 0; nt < 4; nt++) {
                    int np = nt >> 1, e = (nt & 1) * 2;
                    mma16816(acc[mt][nt], al[mt], bh4[np][e], bh4[np][e + 1]);
                }
            }
        }
    }
    __syncthreads();

    // ---- epilogue: frags -> smem staging (bias, mode scale) ----
    float* sD = (float*)dynsmem;
    int g = lane >> 2, cb = (lane & 3) * 2;
    #pragma unroll
    for (int mt = 0; mt < 4; mt++)
        #pragma unroll
        for (int nt = 0; nt < 4; nt++)
            #pragma unroll
            for (int r = 0; r < 4; r++) {
                int row = m_base + mt * 16 + (r >> 1) * 8 + g;
                int col = n_base + nt * 8 + cb + (r & 1);
                float v = acc[mt][nt][r] + ar.bias[n0 + col];
                if (MODE == 0) v *= 0.125f * LOG2E;   // 1/sqrt(64) and exp2 domain
                sD[row * 132 + col] = v;
            }
    __syncthreads();

    // ---- smem -> global ----
    int b  = m0 >> 11;
    int l0 = m0 & (LL - 1);
    if (MODE == 0 || MODE == 1) {
        uint32_t* dh = (MODE == 0) ? g_qh : g_kh;
        uint32_t* dl = (MODE == 0) ? g_ql : g_kl;
        for (int idx = tid; idx < 8192; idx += 256) {
            int dp = idx & 31;
            int hseg = (idx >> 5) & 1;
            int mi = idx >> 6;
            int nl = hseg * 64 + dp * 2;
            float v0 = sD[mi * 132 + nl], v1 = sD[mi * 132 + nl + 1];
            float h0 = bhi(v0), h1 = bhi(v1);
            int n = n0 + nl, h = n >> 6;
            size_t o = (size_t)((b * NHH + h) * LL + l0 + mi) * 32 + dp;
            dh[o] = pack2(h0, h1);
            dl[o] = pack2(v0 - h0, v1 - h1);
        }
    } else if (MODE == 2) {
        // V: single fp16 (PV uses 2-term fp16 scheme; V rounding 2^-11)
        for (int idx = tid; idx < 8192; idx += 256) {
            int lp = idx & 63;
            int nl = idx >> 6;
            float v0 = sD[(2 * lp) * 132 + nl], v1 = sD[(2 * lp + 1) * 132 + nl];
            int n = n0 + nl, h = n >> 6, d = n & 63;
            size_t o = (size_t)((b * NHH + h) * HDD + d) * (LL / 2) + l0 / 2 + lp;
            g_vh[o] = pack2h(v0, v1);
        }
    } else {
        for (int idx = tid; idx < TGM * TGN; idx += 256) {
            int nl = idx & 127, mi = idx >> 7;
            out[(size_t)(m0 + mi) * HH + n0 + nl] = sD[mi * 132 + nl];
        }
    }
}

__global__ void __launch_bounds__(256)
qkv_kernel(const float* __restrict__ bq, const float* __restrict__ bk,
           const float* __restrict__ bv)
{
    extern __shared__ char dynsmem[];
    int mode = blockIdx.z;
    TGArgs ar;
    ar.Ah = g_xh; ar.Al = g_xl;
    ar.Bh = g_wh + (size_t)mode * HH * KP;
    ar.Bl = g_wl + (size_t)mode * HH * KP;
    ar.bias = (mode == 0) ? bq : (mode == 1) ? bk : bv;
    int n0 = blockIdx.x * TGN, m0 = blockIdx.y * TGM;
    if (mode == 0)      tgemm_body<0>(ar, nullptr, n0, m0, dynsmem);
    else if (mode == 1) tgemm_body<1>(ar, nullptr, n0, m0, dynsmem);
    else                tgemm_body<2>(ar, nullptr, n0, m0, dynsmem);
}

__global__ void __launch_bounds__(256)
oproj_kernel(const float* __restrict__ bo, float* __restrict__ out)
{
    extern __shared__ char dynsmem[];
    TGArgs ar;
    ar.Ah = g_atth; ar.Al = g_attl;
    ar.Bh = g_wh + (size_t)3 * HH * KP;
    ar.Bl = g_wl + (size_t)3 * HH * KP;
    ar.bias = bo;
    tgemm_body<3>(ar, out, blockIdx.x * TGN, blockIdx.y * TGM, dynsmem);
}

// ---------------- tensor-core flash attention (256 thr, 128 q-rows) -----------
// stage: KH(bf16) +0, KL(bf16) +9216, VH(fp16) +18432  -> 27648 B per stage
#define FROWB 144
#define FQH 0
#define FQL 18432                 // Q: 128 rows x 144 per half
#define FSTG0 36864
#define FSTGB 27648
#define FBIAS (FSTG0 + 2*FSTGB)   // 92160; 2 x 256B
#define FL_SMEM (FBIAS + 512)     // 92672

__global__ void __launch_bounds__(256, 2)
flash_kernel()
{
    extern __shared__ char fsm[];
    uint32_t sb = smem_u32(fsm);
    int tid = threadIdx.x;
    int lane = tid & 31;
    int wid = tid >> 5;          // 0..7, each warp owns 16 q-rows
    int bh = blockIdx.y;
    int q0 = blockIdx.x * 128;

    const char* qh = (const char*)g_qh;
    const char* ql = (const char*)g_ql;
    const char* kh = (const char*)g_kh;
    const char* kl = (const char*)g_kl;
    const char* vh = (const char*)g_vh;

    // K/V/bias stage loader (async): 1536 16B-chunks, 6 per thread
    auto load_kv = [&](int c) {
        uint32_t dst = sb + FSTG0 + (c & 1) * FSTGB;
        int k0 = c * 64;
        #pragma unroll
        for (int i = 0; i < 6; i++) {
            int idx = tid + i * 256;         // 0..1535
            int arr = idx >> 9;              // 0:KH 1:KL 2:VH
            int e = idx & 511;
            int r = e >> 3, q8 = e & 7;
            uint32_t so = (uint32_t)(arr * 9216 + r * FROWB + q8 * 16);
            if (arr < 2) {
                size_t gk = (size_t)(bh * LL + k0 + r) * 128 + q8 * 16;
                cpa16(dst + so, (arr == 0 ? kh : kl) + gk);
            } else {
                size_t gv = (size_t)(bh * HDD + r) * (LL * 2) + k0 * 2 + q8 * 16;
                cpa16(dst + so, vh + gv);
            }
        }
        if (tid < 16)
            cpa16(sb + FBIAS + (c & 1) * 256 + tid * 16,
                  (const char*)g_bias + (size_t)bh * LL * 4 + c * 256 + tid * 16);
        CPA_COMMIT();
    };

    // Q tile (once, synchronous): 128 rows hi+lo = 2048 chunks
    #pragma unroll
    for (int i = 0; i < 8; i++) {
        int idx = tid + i * 256;
        int half = idx >> 10;
        int e = idx & 1023;
        int r = e >> 3, q8 = e & 7;
        size_t go = (size_t)(bh * LL + q0 + r) * 128 + q8 * 16;
        *(uint4*)(fsm + (half ? FQL : FQH) + r * FROWB + q8 * 16) =
            *(const uint4*)((half ? ql : qh) + go);
    }
    load_kv(0);
    __syncthreads();   // Q visible for fragment hoist

    int t8 = lane >> 3;
    uint32_t qa = sb + FQH +
        (uint32_t)((wid * 16 + (t8 & 1) * 8 + (lane & 7)) * FROWB + (t8 >> 1) * 16);
    uint32_t kb_rel =
        (uint32_t)(((t8 >> 1) * 8 + (lane & 7)) * FROWB + (t8 & 1) * 16);

    // hoist Q fragments (Q smem never overwritten)
    uint32_t qfh[4][4], qfl[4][4];
    #pragma unroll
    for (int kk = 0; kk < 4; kk++) {
        ldsm4(qfh[kk], qa + kk * 32);
        ldsm4(qfl[kk], qa + kk * 32 + (FQL - FQH));
    }

    float o[8][4];
    #pragma unroll
    for (int i = 0; i < 8; i++)
        #pragma unroll
        for (int r = 0; r < 4; r++) o[i][r] = 0.f;
    float m0r = -1e30f, m1r = -1e30f, ls0 = 0.f, ls1 = 0.f;

    for (int c = 0; c < 32; c++) {
        CPA_WAIT0();             // stage c fully arrived (only outstanding group)
        __syncthreads();         // stage c visible; all warps done reading c-1
        if (c < 31) load_kv(c + 1);   // overwrite stage c-1 buffer; overlaps compute

        uint32_t stg = sb + FSTG0 + (c & 1) * FSTGB;
        uint32_t kb = stg + kb_rel;
        uint32_t vb = stg + 18432 + kb_rel;
        const float* sbias = (const float*)(fsm + FBIAS + (c & 1) * 256);
        int cb = (lane & 3) * 2;

        // ---- S = Q K^T (3-term bf16 split), bias pre-loaded as accumulator ----
        float s[8][4];
        #pragma unroll
        for (int nf = 0; nf < 8; nf++) {
            float b0 = sbias[nf * 8 + cb], b1 = sbias[nf * 8 + cb + 1];
            s[nf][0] = b0; s[nf][1] = b1;
            s[nf][2] = b0; s[nf][3] = b1;
        }

        #pragma unroll
        for (int kk = 0; kk < 4; kk++) {
            #pragma unroll
            for (int nb = 0; nb < 4; nb++) {
                uint32_t bh4[4], bl4[4];
                uint32_t ba = kb + nb * (16 * FROWB) + kk * 32;
                ldsm4(bh4, ba);
                ldsm4(bl4, ba + 9216);
                mma16816(s[2 * nb],     qfh[kk], bh4[0], bh4[1]);
                mma16816(s[2 * nb + 1], qfh[kk], bh4[2], bh4[3]);
                mma16816(s[2 * nb],     qfh[kk], bl4[0], bl4[1]);
                mma16816(s[2 * nb + 1], qfh[kk], bl4[2], bl4[3]);
                mma16816(s[2 * nb],     qfl[kk], bh4[0], bh4[1]);
                mma16816(s[2 * nb + 1], qfl[kk], bh4[2], bh4[3]);
            }
        }

        // ---- online softmax in exp2 domain ----
        float mx0 = -1e30f, mx1 = -1e30f;
        #pragma unroll
        for (int nf = 0; nf < 8; nf++) {
            mx0 = fmaxf(mx0, fmaxf(s[nf][0], s[nf][1]));
            mx1 = fmaxf(mx1, fmaxf(s[nf][2], s[nf][3]));
        }
        mx0 = fmaxf(mx0, __shfl_xor_sync(0xffffffffu, mx0, 1));
        mx0 = fmaxf(mx0, __shfl_xor_sync(0xffffffffu, mx0, 2));
        mx1 = fmaxf(mx1, __shfl_xor_sync(0xffffffffu, mx1, 1));
        mx1 = fmaxf(mx1, __shfl_xor_sync(0xffffffffu, mx1, 2));
        float mn0 = fmaxf(m0r, mx0), mn1 = fmaxf(m1r, mx1);
        float c0 = ex2(m0r - mn0), c1 = ex2(m1r - mn1);
        m0r = mn0; m1r = mn1;
        ls0 *= c0; ls1 *= c1;
        #pragma unroll
        for (int nf = 0; nf < 8; nf++) {
            o[nf][0] *= c0; o[nf][1] *= c0;
            o[nf][2] *= c1; o[nf][3] *= c1;
        }
        float rs0 = 0.f, rs1 = 0.f;
        #pragma unroll
        for (int nf = 0; nf < 8; nf++) {
            s[nf][0] = ex2(s[nf][0] - mn0);
            s[nf][1] = ex2(s[nf][1] - mn0);
            s[nf][2] = ex2(s[nf][2] - mn1);
            s[nf][3] = ex2(s[nf][3] - mn1);
            rs0 += s[nf][0] + s[nf][1];
            rs1 += s[nf][2] + s[nf][3];
        }
        rs0 += __shfl_xor_sync(0xffffffffu, rs0, 1);
        rs0 += __shfl_xor_sync(0xffffffffu, rs0, 2);
        rs1 += __shfl_xor_sync(0xffffffffu, rs1, 1);
        rs1 += __shfl_xor_sync(0xffffffffu, rs1, 2);
        ls0 += rs0; ls1 += rs1;

        // ---- O += P V : 2-term fp16 (P = ph+pl exact, V single fp16) ----
        #pragma unroll
        for (int j = 0; j < 4; j++) {
            uint32_t aph[4], apl[4];
            splitpairh(s[2*j][0],   s[2*j][1],   aph[0], apl[0]);
            splitpairh(s[2*j][2],   s[2*j][3],   aph[1], apl[1]);
            splitpairh(s[2*j+1][0], s[2*j+1][1], aph[2], apl[2]);
            splitpairh(s[2*j+1][2], s[2*j+1][3], aph[3], apl[3]);
            #pragma unroll
            for (int nb = 0; nb < 4; nb++) {
                uint32_t vh4[4];
                uint32_t va = vb + nb * (16 * FROWB) + j * 32;
                ldsm4(vh4, va);
                mma16816h(o[2 * nb],     aph, vh4[0], vh4[1]);
                mma16816h(o[2 * nb + 1], aph, vh4[2], vh4[3]);
                mma16816h(o[2 * nb],     apl, vh4[0], vh4[1]);
                mma16816h(o[2 * nb + 1], apl, vh4[2], vh4[3]);
            }
        }
    }

    // ---- finalize: O /= l, write split bf16 directly (O-proj A operand) ----
    int b = bh >> 4;
    int h = bh & 15;
    float i0 = 1.f / ls0, i1 = 1.f / ls1;
    int g = lane >> 2, cb = (lane & 3) * 2;
    int row0 = q0 + wid * 16 + g;
    #pragma unroll
    for (int nf = 0; nf < 8; nf++) {
        int colp = (h * HDD + nf * 8 + cb) >> 1;
        float a0 = o[nf][0] * i0, a1 = o[nf][1] * i0;
        float b0 = o[nf][2] * i1, b1 = o[nf][3] * i1;
        float ah0 = bhi(a0), ah1 = bhi(a1), bh0 = bhi(b0), bh1 = bhi(b1);
        size_t r0o = (size_t)(b * LL + row0) * KP + colp;
        size_t r1o = (size_t)(b * LL + row0 + 8) * KP + colp;
        g_atth[r0o] = pack2(ah0, ah1);
        g_attl[r0o] = pack2(a0 - ah0, a1 - ah1);
        g_atth[r1o] = pack2(bh0, bh1);
        g_attl[r1o] = pack2(b0 - bh0, b1 - bh1);
    }
}

// ---------------- launch ------------------------------------------------------
extern "C" void kernel_launch(void* const* d_in, const int* in_sizes, int n_in,
                              void* d_out, int out_size)
{
    const float* x     = (const float*)d_in[0];
    const float* amask = (const float*)d_in[1];
    const int*   err   = (const int*)  d_in[2];
    const float* Wq    = (const float*)d_in[3];
    const float* bq    = (const float*)d_in[4];
    const float* Wk    = (const float*)d_in[5];
    const float* bk    = (const float*)d_in[6];
    const float* Wv    = (const float*)d_in[7];
    const float* bv    = (const float*)d_in[8];
    const float* Wo    = (const float*)d_in[9];
    const float* bo    = (const float*)d_in[10];
    const float* dbias = (const float*)d_in[11];
    const float* Wg    = (const float*)d_in[12];
    const float* bg    = (const float*)d_in[13];
    float* out = (float*)d_out;

    cudaFuncSetAttribute(qkv_kernel,   cudaFuncAttributeMaxDynamicSharedMemorySize, TG_SMEM);
    cudaFuncSetAttribute(oproj_kernel, cudaFuncAttributeMaxDynamicSharedMemorySize, TG_SMEM);
    cudaFuncSetAttribute(flash_kernel, cudaFuncAttributeMaxDynamicSharedMemorySize, FL_SMEM);

    xsplit_kernel<<<MM * HH / 512, 256>>>(x);

    dim3 tb(32, 8);
    dim3 tg(HH / 32, HH / 32, 4);
    wtrans_kernel<<<tg, tb>>>(Wq, Wk, Wv, Wo);

    gate_bias_kernel<<<MM, 128>>>(x, amask, err, Wg, bg, dbias);

    dim3 qgrid(HH / TGN, MM / TGM, 3);   // 768 CTAs
    qkv_kernel<<<qgrid, 256, TG_SMEM>>>(bq, bk, bv);

    dim3 fgrid(LL / 128, BH);            // 512 CTAs, 256 threads
    flash_kernel<<<fgrid, 256, FL_SMEM>>>();

    dim3 ogrid(HH / TGN, MM / TGM);      // 256 CTAs
    oproj_kernel<<<ogrid, 256, TG_SMEM>>>(bo, out);
}